// round 9
// baseline (speedup 1.0000x reference)
#include <cuda_runtime.h>
#include <math.h>
#include <stdint.h>

#define BSZ  4096
#define KSEL 200

// ---- scratch (__device__ globals; no allocations allowed) ----
__device__ float g_S[(size_t)BSZ * BSZ];          // 64 MB similarity matrix
__device__ float g_perrow[BSZ];
__device__ float g_validf[BSZ];

// packed f32x2 helpers (plain PTX, valid on compute_103)
__device__ __forceinline__ void fma2(unsigned long long& d,
                                     unsigned long long a,
                                     unsigned long long b) {
    asm("fma.rn.f32x2 %0, %1, %2, %0;" : "+l"(d) : "l"(a), "l"(b));
}
__device__ __forceinline__ unsigned long long splat2(float x) {
    unsigned long long r;
    asm("mov.b64 %0, {%1, %1};" : "=l"(r) : "f"(x));
    return r;
}

// ===========================================================================
// Symmetric GEMM: S = F * F^T.  128x128 tiles, 256 threads, 8x8 per thread,
// packed f32x2 accumulation. Triangular 1D grid (528 tiles), mirror written
// via chunked smem transpose. K processed in 8 chunks of 16.
// (Proven 86us in R2 -- kept verbatim.)
// ===========================================================================
__global__ __launch_bounds__(256, 2) void gemm_sym(const float* __restrict__ F) {
    int lin = blockIdx.x;
    int by = 0;
    while (lin >= 32 - by) { lin -= 32 - by; by++; }
    int bx = by + lin;
    const int bi = by * 128, bj = bx * 128;

    __shared__ float sh[4224];               // As[16][132] | Bs[16][132]; reused
    float* As = sh;
    float* Bs = sh + 2112;

    const int tid = threadIdx.x;
    const int tx = tid & 15, ty = tid >> 4;

    unsigned long long acc2[4][8];
#pragma unroll
    for (int p = 0; p < 4; p++)
#pragma unroll
        for (int c = 0; c < 8; c++) acc2[p][c] = 0ULL;

    const float4* F4 = reinterpret_cast<const float4*>(F);
    const int kq = tid & 3;
    const int lm = tid >> 2;

#pragma unroll 1
    for (int chunk = 0; chunk < 8; chunk++) {
        if (chunk) __syncthreads();
        float4 va0 = F4[(size_t)(bi + lm) * 32 + chunk * 4 + kq];
        float4 va1 = F4[(size_t)(bi + lm + 64) * 32 + chunk * 4 + kq];
        float4 vb0 = F4[(size_t)(bj + lm) * 32 + chunk * 4 + kq];
        float4 vb1 = F4[(size_t)(bj + lm + 64) * 32 + chunk * 4 + kq];
        {
            int kb = kq * 4;
            As[(kb + 0) * 132 + lm] = va0.x; As[(kb + 1) * 132 + lm] = va0.y;
            As[(kb + 2) * 132 + lm] = va0.z; As[(kb + 3) * 132 + lm] = va0.w;
            As[(kb + 0) * 132 + lm + 64] = va1.x; As[(kb + 1) * 132 + lm + 64] = va1.y;
            As[(kb + 2) * 132 + lm + 64] = va1.z; As[(kb + 3) * 132 + lm + 64] = va1.w;
            Bs[(kb + 0) * 132 + lm] = vb0.x; Bs[(kb + 1) * 132 + lm] = vb0.y;
            Bs[(kb + 2) * 132 + lm] = vb0.z; Bs[(kb + 3) * 132 + lm] = vb0.w;
            Bs[(kb + 0) * 132 + lm + 64] = vb1.x; Bs[(kb + 1) * 132 + lm + 64] = vb1.y;
            Bs[(kb + 2) * 132 + lm + 64] = vb1.z; Bs[(kb + 3) * 132 + lm + 64] = vb1.w;
        }
        __syncthreads();

        const float4* As4 = reinterpret_cast<const float4*>(As);
        const float4* Bs4 = reinterpret_cast<const float4*>(Bs);
#pragma unroll
        for (int k = 0; k < 16; k++) {
            float4 av0 = As4[k * 33 + ty];
            float4 av1 = As4[k * 33 + 16 + ty];
            float4 bv0 = Bs4[k * 33 + tx];
            float4 bv1 = Bs4[k * 33 + 16 + tx];
            unsigned long long A0 = reinterpret_cast<const ulonglong2*>(&av0)->x;
            unsigned long long A1 = reinterpret_cast<const ulonglong2*>(&av0)->y;
            unsigned long long A2 = reinterpret_cast<const ulonglong2*>(&av1)->x;
            unsigned long long A3 = reinterpret_cast<const ulonglong2*>(&av1)->y;
            unsigned long long B[8];
            B[0] = splat2(bv0.x); B[1] = splat2(bv0.y);
            B[2] = splat2(bv0.z); B[3] = splat2(bv0.w);
            B[4] = splat2(bv1.x); B[5] = splat2(bv1.y);
            B[6] = splat2(bv1.z); B[7] = splat2(bv1.w);
#pragma unroll
            for (int c = 0; c < 8; c++) {
                fma2(acc2[0][c], A0, B[c]);
                fma2(acc2[1][c], A1, B[c]);
                fma2(acc2[2][c], A2, B[c]);
                fma2(acc2[3][c], A3, B[c]);
            }
        }
    }

    auto accf = [&](int p, int c, int half) -> float {
        float2 f = *reinterpret_cast<float2*>(&acc2[p][c]);
        return half ? f.y : f.x;
    };
    auto rowOf = [&](int p, int h) -> int {
        return (p < 2) ? (ty * 4 + 2 * p + h) : (64 + ty * 4 + 2 * (p - 2) + h);
    };

#pragma unroll
    for (int p = 0; p < 4; p++)
#pragma unroll
        for (int h = 0; h < 2; h++) {
            int r = rowOf(p, h);
            float4 w0 = make_float4(accf(p, 0, h), accf(p, 1, h), accf(p, 2, h), accf(p, 3, h));
            float4 w1 = make_float4(accf(p, 4, h), accf(p, 5, h), accf(p, 6, h), accf(p, 7, h));
            *reinterpret_cast<float4*>(&g_S[(size_t)(bi + r) * BSZ + bj + tx * 4]) = w0;
            *reinterpret_cast<float4*>(&g_S[(size_t)(bi + r) * BSZ + bj + 64 + tx * 4]) = w1;
        }

    if (bx != by) {
#pragma unroll 1
        for (int q = 0; q < 4; q++) {
            __syncthreads();
            int cbase = (q < 2) ? (tx * 4 - 32 * q) : (64 + tx * 4 - 32 * q);
            if (cbase >= 0 && cbase < 32) {
                int coff = (q < 2) ? 0 : 4;
#pragma unroll
                for (int j = 0; j < 4; j++)
#pragma unroll
                    for (int p = 0; p < 4; p++) {
                        sh[(cbase + j) * 132 + rowOf(p, 0)] = accf(p, coff + j, 0);
                        sh[(cbase + j) * 132 + rowOf(p, 1)] = accf(p, coff + j, 1);
                    }
            }
            __syncthreads();
            int cl = tid >> 3, f = tid & 7;
#pragma unroll
            for (int kk = 0; kk < 4; kk++) {
                int f4 = f + kk * 8;
                float4 v = *reinterpret_cast<const float4*>(&sh[cl * 132 + f4 * 4]);
                *reinterpret_cast<float4*>(
                    &g_S[(size_t)(bj + q * 32 + cl) * BSZ + bi + f4 * 4]) = v;
            }
        }
    }
}

// ===========================================================================
// Per-row pass: fixed-threshold bracket (counts fused into pass 1), exact
// tie-aware rank on candidates. 9-ary bisection fallback keeps it exact on
// any data distribution.
// ===========================================================================
__global__ __launch_bounds__(256) void row_kernel(const int* __restrict__ labels) {
    __shared__ int   s_i[8][8];
    __shared__ float s_f[8][4];
    __shared__ unsigned scnt[8][8];
    __shared__ unsigned scounts[8];
    __shared__ float cand[2048];
    __shared__ unsigned ccount;
    __shared__ float sT;
    __shared__ unsigned sgt;

    const int i = blockIdx.x, tid = threadIdx.x;
    const int lane = tid & 31, warp = tid >> 5;
    const int myLab = labels[i];

    const float4* S4 = reinterpret_cast<const float4*>(g_S + (size_t)i * BSZ);
    const int4*   L4 = reinterpret_cast<const int4*>(labels);

    float v[16];
    unsigned negm = 0;
#pragma unroll
    for (int q = 0; q < 4; q++) {
        int idx = tid + q * 256;
        float4 x = S4[idx];
        int4   l = L4[idx];
        v[q * 4 + 0] = x.x; v[q * 4 + 1] = x.y; v[q * 4 + 2] = x.z; v[q * 4 + 3] = x.w;
        if (l.x != myLab) negm |= 1u << (q * 4 + 0);
        if (l.y != myLab) negm |= 1u << (q * 4 + 1);
        if (l.z != myLab) negm |= 1u << (q * 4 + 2);
        if (l.w != myLab) negm |= 1u << (q * 4 + 3);
    }

    // ---- pass 1: max + threshold counts + positive sums (one loop) ----
    const float T1 = 0.10f, T2 = 0.13f, T3 = 0.16f, T4 = 0.19f;
    float mloc = -1e30f, psum = 0.0f, pcnt = 0.0f;
    int tc1 = 0, tc2 = 0, tc3 = 0, tc4 = 0;
    int pc1 = 0, pc2 = 0, pc3 = 0, pc4 = 0;
#pragma unroll
    for (int e = 0; e < 16; e++) {
        float x = v[e];
        mloc = fmaxf(mloc, x);
        tc1 += x > T1; tc2 += x > T2; tc3 += x > T3; tc4 += x > T4;
        if (!((negm >> e) & 1u)) {
            int j = (tid + (e >> 2) * 256) * 4 + (e & 3);
            if (j != i) {
                psum += x; pcnt += 1.0f;
                pc1 += x > T1; pc2 += x > T2; pc3 += x > T3; pc4 += x > T4;
            }
        }
    }
#pragma unroll
    for (int o = 16; o; o >>= 1) {
        mloc = fmaxf(mloc, __shfl_xor_sync(0xFFFFFFFFu, mloc, o));
        psum += __shfl_xor_sync(0xFFFFFFFFu, psum, o);
        pcnt += __shfl_xor_sync(0xFFFFFFFFu, pcnt, o);
    }
    tc1 = __reduce_add_sync(0xFFFFFFFFu, tc1); tc2 = __reduce_add_sync(0xFFFFFFFFu, tc2);
    tc3 = __reduce_add_sync(0xFFFFFFFFu, tc3); tc4 = __reduce_add_sync(0xFFFFFFFFu, tc4);
    pc1 = __reduce_add_sync(0xFFFFFFFFu, pc1); pc2 = __reduce_add_sync(0xFFFFFFFFu, pc2);
    pc3 = __reduce_add_sync(0xFFFFFFFFu, pc3); pc4 = __reduce_add_sync(0xFFFFFFFFu, pc4);
    if (lane == 0) {
        s_i[warp][0] = tc1; s_i[warp][1] = tc2; s_i[warp][2] = tc3; s_i[warp][3] = tc4;
        s_i[warp][4] = pc1; s_i[warp][5] = pc2; s_i[warp][6] = pc3; s_i[warp][7] = pc4;
        s_f[warp][0] = mloc; s_f[warp][1] = psum; s_f[warp][2] = pcnt;
    }
    __syncthreads();
    float m = s_f[0][0]; psum = s_f[0][1]; pcnt = s_f[0][2];
    int cN1 = s_i[0][0] - s_i[0][4], cN2 = s_i[0][1] - s_i[0][5];
    int cN3 = s_i[0][2] - s_i[0][6], cN4 = s_i[0][3] - s_i[0][7];
#pragma unroll
    for (int w = 1; w < 8; w++) {
        m = fmaxf(m, s_f[w][0]); psum += s_f[w][1]; pcnt += s_f[w][2];
        cN1 += s_i[w][0] - s_i[w][4]; cN2 += s_i[w][1] - s_i[w][5];
        cN3 += s_i[w][2] - s_i[w][6]; cN4 += s_i[w][3] - s_i[w][7];
    }
    cN1 -= 1; cN2 -= 1; cN3 -= 1; cN4 -= 1;      // exclude self (s==1 above all thresholds)
    const int cnt = (int)pcnt;
    const int negcnt = BSZ - 1 - cnt;
    const float lsum = 10.0f * psum - 10.0f * pcnt * m;

    float nsum = 0.0f, esum = 0.0f, tail = 0.0f;

    if (negcnt <= KSEL) {
#pragma unroll
        for (int e = 0; e < 16; e++) {
            int j = (tid + (e >> 2) * 256) * 4 + (e & 3);
            float lg = (v[e] - m) * 10.0f;
            if ((negm >> e) & 1u)      nsum += __expf(lg);
            else if (j != i)           esum += __expf(lg);
        }
#pragma unroll
        for (int o = 16; o; o >>= 1) {
            nsum += __shfl_xor_sync(0xFFFFFFFFu, nsum, o);
            esum += __shfl_xor_sync(0xFFFFFFFFu, esum, o);
        }
        __syncthreads();
        if (lane == 0) { s_f[warp][0] = nsum; s_f[warp][1] = esum; }
        __syncthreads();
        nsum = 0.0f; esum = 0.0f;
#pragma unroll
        for (int w = 0; w < 8; w++) { nsum += s_f[w][0]; esum += s_f[w][1]; }
    } else {
        // ---- determine bracket (lo, hi], cntAbove = #neg > hi ----
        float lo = 0.0f, hi = 0.0f; int cntAbove = 0; bool fast = false;
        {
            const float tj[5] = {-2.0f, T1, T2, T3, T4};
            const int   cN[5] = {negcnt, cN1, cN2, cN3, cN4};
            int js = -1;
#pragma unroll
            for (int j = 4; j >= 1; j--) if (cN[j] < KSEL) js = j;
            if (js >= 2) {
                int gap = cN[js - 1] - cN[js];
                if (gap >= 1 && gap <= 2048) {
                    lo = tj[js - 1]; hi = tj[js]; cntAbove = cN[js]; fast = true;
                }
            }
        }
        if (!fast) {
            // fallback: 9-ary bisection (exact for any data)
            float blo = -1.01f, bhi = 1.01f;
            int cLo = negcnt, cHi = 0;
            for (int round = 0; round < 8 && (cLo - cHi) > 48; round++) {
                float w9 = (bhi - blo) * (1.0f / 9.0f);
                float t[8];
#pragma unroll
                for (int j = 0; j < 8; j++) t[j] = blo + w9 * (float)(j + 1);
                unsigned c[8] = {0,0,0,0,0,0,0,0};
#pragma unroll
                for (int e = 0; e < 16; e++)
                    if ((negm >> e) & 1u) {
                        float x = v[e];
#pragma unroll
                        for (int j = 0; j < 8; j++) c[j] += (x > t[j]);
                    }
#pragma unroll
                for (int j = 0; j < 8; j++) c[j] = __reduce_add_sync(0xFFFFFFFFu, c[j]);
                if (lane == 0)
#pragma unroll
                    for (int j = 0; j < 8; j++) scnt[warp][j] = c[j];
                __syncthreads();
                if (tid < 8) {
                    unsigned s = 0;
#pragma unroll
                    for (int wq = 0; wq < 8; wq++) s += scnt[wq][tid];
                    scounts[tid] = s;
                }
                __syncthreads();
                int jstar = 8;
#pragma unroll
                for (int j = 7; j >= 0; j--) if ((int)scounts[j] < KSEL) jstar = j;
                if (jstar == 8)      { blo = t[7]; cLo = (int)scounts[7]; }
                else if (jstar == 0) { bhi = t[0]; cHi = (int)scounts[0]; }
                else { blo = t[jstar - 1]; cLo = (int)scounts[jstar - 1];
                       bhi = t[jstar];     cHi = (int)scounts[jstar]; }
                __syncthreads();
            }
            lo = blo; hi = bhi; cntAbove = cHi;
        }

        // ---- pass 2: exp sums + candidate gather ----
        if (tid == 0) ccount = 0;
        __syncthreads();
#pragma unroll
        for (int e = 0; e < 16; e++) {
            float x = v[e];
            if ((negm >> e) & 1u) {
                if (x > hi) nsum += __expf((x - m) * 10.0f);
                else if (x > lo) {
                    unsigned u = atomicAdd(&ccount, 1u);
                    if (u < 2048) cand[u] = x;
                }
            } else {
                int j = (tid + (e >> 2) * 256) * 4 + (e & 3);
                if (j != i) esum += __expf((x - m) * 10.0f);
            }
        }
        __syncthreads();
        const int c = (int)min(ccount, 2048u);

        // ---- exact tie-aware rank among candidates ----
        for (int t = tid; t < c; t += 256) {
            float x = cand[t];
            int gt = 0, eq = 0;
            for (int u = 0; u < c; u++) {
                float y = cand[u];
                gt += (y > x); eq += (y == x);
            }
            if (cntAbove + gt < KSEL && KSEL <= cntAbove + gt + eq) {
                sT = x; sgt = (unsigned)(cntAbove + gt);
            }
        }
        __syncthreads();
        const float T = sT;
        const int ties = KSEL - (int)sgt;
        for (int t = tid; t < c; t += 256)
            if (cand[t] > T) nsum += __expf((cand[t] - m) * 10.0f);
        tail = (float)ties * __expf((T - m) * 10.0f);

#pragma unroll
        for (int o = 16; o; o >>= 1) {
            nsum += __shfl_xor_sync(0xFFFFFFFFu, nsum, o);
            esum += __shfl_xor_sync(0xFFFFFFFFu, esum, o);
        }
        __syncthreads();
        if (lane == 0) { s_f[warp][0] = nsum; s_f[warp][1] = esum; }
        __syncthreads();
        nsum = 0.0f; esum = 0.0f;
#pragma unroll
        for (int w = 0; w < 8; w++) { nsum += s_f[w][0]; esum += s_f[w][1]; }
    }

    if (tid == 0) {
        float denom = esum + nsum + tail;
        bool valid = (myLab > 0) && (cnt > 0);
        float mlpp = (cnt > 0) ? (lsum / pcnt) : 0.0f;
        g_perrow[i] = valid ? (-2.0f * (mlpp - logf(denom))) : 0.0f;
        g_validf[i] = valid ? 1.0f : 0.0f;
    }
}

// ===========================================================================
// Deterministic final reduction
// ===========================================================================
__global__ void finalize(float* __restrict__ out) {
    __shared__ float sp[256], sv[256];
    int tid = threadIdx.x;
    float ps = 0.0f, vs = 0.0f;
    for (int j = tid; j < BSZ; j += 256) { ps += g_perrow[j]; vs += g_validf[j]; }
    sp[tid] = ps; sv[tid] = vs;
    __syncthreads();
#pragma unroll
    for (int o = 128; o; o >>= 1) {
        if (tid < o) { sp[tid] += sp[tid + o]; sv[tid] += sv[tid + o]; }
        __syncthreads();
    }
    if (tid == 0) out[0] = sp[0] / sv[0];
}

// ===========================================================================
extern "C" void kernel_launch(void* const* d_in, const int* in_sizes, int n_in,
                              void* d_out, int out_size) {
    (void)in_sizes; (void)n_in; (void)out_size;
    const float* F      = (const float*)d_in[0];
    const int*   labels = (const int*)d_in[1];
    float*       out    = (float*)d_out;

    gemm_sym<<<528, 256>>>(F);
    row_kernel<<<BSZ, 256>>>(labels);
    finalize<<<1, 256>>>(out);
}

// round 11
// speedup vs baseline: 1.1741x; 1.1741x over previous
#include <cuda_runtime.h>
#include <math.h>
#include <stdint.h>

#define BSZ  4096
#define KSEL 200
#define CLO  0.10f
#define CHI  0.22f
#define CAP  768

// ---- scratch (__device__ globals; no allocations allowed) ----
__device__ float4 g_part[(size_t)BSZ * 32];     // per (row, tilecol): psum, e_pos, e_hi, packed(pcnt|chi<<16)
__device__ float  g_cand[(size_t)BSZ * CAP];    // negative values in (CLO, CHI]
__device__ int    g_ccnt[BSZ];
__device__ float  g_perrow[BSZ];
__device__ float  g_validf[BSZ];

// packed f32x2 helpers (plain PTX, valid on compute_103)
__device__ __forceinline__ void fma2(unsigned long long& d,
                                     unsigned long long a,
                                     unsigned long long b) {
    asm("fma.rn.f32x2 %0, %1, %2, %0;" : "+l"(d) : "l"(a), "l"(b));
}
__device__ __forceinline__ unsigned long long splat2(float x) {
    unsigned long long r;
    asm("mov.b64 %0, {%1, %1};" : "=l"(r) : "f"(x));
    return r;
}

// ===========================================================================
// init: zero per-row candidate counters (must happen every launch)
// ===========================================================================
__global__ void init_k() {
    int i = blockIdx.x * 256 + threadIdx.x;
    if (i < BSZ) g_ccnt[i] = 0;
}

// ===========================================================================
// Fused GEMM + statistics epilogue. S = F F^T, 128x128 tiles, triangular
// grid (528). Mainloop identical to the proven R2 f32x2 kernel. The epilogue
// does NOT store S; it emits per-(row, tilecol) partials and appends
// candidate negatives to per-row buffers (direct role + mirror role).
// ===========================================================================
__global__ __launch_bounds__(256, 2) void gemm_stats(const float* __restrict__ F,
                                                     const int* __restrict__ labels) {
    int lin = blockIdx.x;
    int by = 0;
    while (lin >= 32 - by) { lin -= 32 - by; by++; }
    int bx = by + lin;
    const int bi = by * 128, bj = bx * 128;

    __shared__ float sh[4224];               // As[16][132] | Bs[16][132]; reused for mirror staging
    __shared__ int labsh[256];               // [0:128) row labels, [128:256) col labels
    float* As = sh;
    float* Bs = sh + 2112;

    const int tid = threadIdx.x;
    const int tx = tid & 15, ty = tid >> 4;

    if (tid < 128) labsh[tid] = labels[bi + tid];
    else           labsh[tid] = labels[bj + tid - 128];

    unsigned long long acc2[4][8];
#pragma unroll
    for (int p = 0; p < 4; p++)
#pragma unroll
        for (int c = 0; c < 8; c++) acc2[p][c] = 0ULL;

    const float4* F4 = reinterpret_cast<const float4*>(F);
    const int kq = tid & 3;
    const int lm = tid >> 2;

#pragma unroll 1
    for (int chunk = 0; chunk < 8; chunk++) {
        __syncthreads();                      // also covers labsh visibility
        float4 va0 = F4[(size_t)(bi + lm) * 32 + chunk * 4 + kq];
        float4 va1 = F4[(size_t)(bi + lm + 64) * 32 + chunk * 4 + kq];
        float4 vb0 = F4[(size_t)(bj + lm) * 32 + chunk * 4 + kq];
        float4 vb1 = F4[(size_t)(bj + lm + 64) * 32 + chunk * 4 + kq];
        {
            int kb = kq * 4;
            As[(kb + 0) * 132 + lm] = va0.x; As[(kb + 1) * 132 + lm] = va0.y;
            As[(kb + 2) * 132 + lm] = va0.z; As[(kb + 3) * 132 + lm] = va0.w;
            As[(kb + 0) * 132 + lm + 64] = va1.x; As[(kb + 1) * 132 + lm + 64] = va1.y;
            As[(kb + 2) * 132 + lm + 64] = va1.z; As[(kb + 3) * 132 + lm + 64] = va1.w;
            Bs[(kb + 0) * 132 + lm] = vb0.x; Bs[(kb + 1) * 132 + lm] = vb0.y;
            Bs[(kb + 2) * 132 + lm] = vb0.z; Bs[(kb + 3) * 132 + lm] = vb0.w;
            Bs[(kb + 0) * 132 + lm + 64] = vb1.x; Bs[(kb + 1) * 132 + lm + 64] = vb1.y;
            Bs[(kb + 2) * 132 + lm + 64] = vb1.z; Bs[(kb + 3) * 132 + lm + 64] = vb1.w;
        }
        __syncthreads();

        const float4* As4 = reinterpret_cast<const float4*>(As);
        const float4* Bs4 = reinterpret_cast<const float4*>(Bs);
#pragma unroll
        for (int k = 0; k < 16; k++) {
            float4 av0 = As4[k * 33 + ty];
            float4 av1 = As4[k * 33 + 16 + ty];
            float4 bv0 = Bs4[k * 33 + tx];
            float4 bv1 = Bs4[k * 33 + 16 + tx];
            unsigned long long A0 = reinterpret_cast<const ulonglong2*>(&av0)->x;
            unsigned long long A1 = reinterpret_cast<const ulonglong2*>(&av0)->y;
            unsigned long long A2 = reinterpret_cast<const ulonglong2*>(&av1)->x;
            unsigned long long A3 = reinterpret_cast<const ulonglong2*>(&av1)->y;
            unsigned long long B[8];
            B[0] = splat2(bv0.x); B[1] = splat2(bv0.y);
            B[2] = splat2(bv0.z); B[3] = splat2(bv0.w);
            B[4] = splat2(bv1.x); B[5] = splat2(bv1.y);
            B[6] = splat2(bv1.z); B[7] = splat2(bv1.w);
#pragma unroll
            for (int c = 0; c < 8; c++) {
                fma2(acc2[0][c], A0, B[c]);
                fma2(acc2[1][c], A1, B[c]);
                fma2(acc2[2][c], A2, B[c]);
                fma2(acc2[3][c], A3, B[c]);
            }
        }
    }

    auto accf = [&](int p, int c, int half) -> float {
        float2 f = *reinterpret_cast<float2*>(&acc2[p][c]);
        return half ? f.y : f.x;
    };
    auto rowOf = [&](int p, int h) -> int {
        return (p < 2) ? (ty * 4 + 2 * p + h) : (64 + ty * 4 + 2 * (p - 2) + h);
    };
    auto colOf = [&](int c) -> int {
        return (c < 4) ? (tx * 4 + c) : (64 + tx * 4 + (c - 4));
    };

    const bool diag = (bx == by);
    __syncthreads();                          // mainloop smem reads done; sh free for staging

    // ---- direct role: rows in block by, tilecol bx (unique writer) ----
#pragma unroll
    for (int p = 0; p < 4; p++)
#pragma unroll
        for (int h = 0; h < 2; h++) {
            int r = rowOf(p, h);
            int labr = labsh[r];
            float ps = 0.0f, ep = 0.0f, eh = 0.0f;
            int pc = 0, ch = 0;
#pragma unroll
            for (int c = 0; c < 8; c++) {
                float x = accf(p, c, h);
                int cloc = colOf(c);
                if (labsh[128 + cloc] == labr) {
                    if (!(diag && cloc == r)) {
                        ps += x; pc++;
                        ep += __expf(10.0f * (x - 1.0f));
                    }
                } else {
                    if (x > CHI) { eh += __expf(10.0f * (x - 1.0f)); ch++; }
                    else if (x > CLO) {
                        int id = atomicAdd(&g_ccnt[bi + r], 1);
                        if (id < CAP) g_cand[(size_t)(bi + r) * CAP + id] = x;
                    }
                }
            }
            int pk = pc | (ch << 16);
#pragma unroll
            for (int off = 8; off; off >>= 1) {
                ps += __shfl_down_sync(0xFFFFFFFFu, ps, off, 16);
                ep += __shfl_down_sync(0xFFFFFFFFu, ep, off, 16);
                eh += __shfl_down_sync(0xFFFFFFFFu, eh, off, 16);
                pk += __shfl_down_sync(0xFFFFFFFFu, pk, off, 16);
            }
            if (tx == 0)
                g_part[(size_t)(bi + r) * 32 + bx] =
                    make_float4(ps, ep, eh, __int_as_float(pk));
        }

    // ---- mirror role: rows in block bx, tilecol by (off-diagonal only) ----
    if (!diag) {
        float2* sh2 = reinterpret_cast<float2*>(sh);
        // round A: psum, e_pos per column
#pragma unroll
        for (int c = 0; c < 8; c++) {
            int cloc = colOf(c);
            int labc = labsh[128 + cloc];
            float ps = 0.0f, ep = 0.0f;
#pragma unroll
            for (int p = 0; p < 4; p++)
#pragma unroll
                for (int h = 0; h < 2; h++) {
                    int r = rowOf(p, h);
                    float x = accf(p, c, h);
                    if (labsh[r] == labc) { ps += x; ep += __expf(10.0f * (x - 1.0f)); }
                }
            sh2[ty * 132 + cloc] = make_float2(ps, ep);
        }
        __syncthreads();
        float mps = 0.0f, mep = 0.0f;
        if (tid < 128)
#pragma unroll
            for (int t = 0; t < 16; t++) {
                float2 v = sh2[t * 132 + tid];
                mps += v.x; mep += v.y;
            }
        __syncthreads();
        // round B: e_hi + packed counts per column, plus candidate appends
#pragma unroll
        for (int c = 0; c < 8; c++) {
            int cloc = colOf(c);
            int labc = labsh[128 + cloc];
            float eh = 0.0f;
            int pc = 0, ch = 0;
#pragma unroll
            for (int p = 0; p < 4; p++)
#pragma unroll
                for (int h = 0; h < 2; h++) {
                    int r = rowOf(p, h);
                    float x = accf(p, c, h);
                    if (labsh[r] == labc) { pc++; }
                    else {
                        if (x > CHI) { eh += __expf(10.0f * (x - 1.0f)); ch++; }
                        else if (x > CLO) {
                            int id = atomicAdd(&g_ccnt[bj + cloc], 1);
                            if (id < CAP) g_cand[(size_t)(bj + cloc) * CAP + id] = x;
                        }
                    }
                }
            sh2[ty * 132 + cloc] = make_float2(eh, (float)(pc | (ch << 16)));
        }
        __syncthreads();
        if (tid < 128) {
            float meh = 0.0f, mpk = 0.0f;
#pragma unroll
            for (int t = 0; t < 16; t++) {
                float2 v = sh2[t * 132 + tid];
                meh += v.x; mpk += v.y;
            }
            g_part[(size_t)(bj + tid) * 32 + by] =
                make_float4(mps, mep, meh, __int_as_float((int)mpk));
        }
    }
}

// ===========================================================================
// Row kernel: one warp per row. Assembles partials, exact tie-aware top-K
// threshold among candidates, reorder-invariant double sums. Exact fallback
// (recompute dots + bisection) for any data outside the candidate window.
// ===========================================================================
__global__ __launch_bounds__(256) void row_kernel(const float* __restrict__ F,
                                                  const int* __restrict__ labels) {
    __shared__ float s_fi[8][128];
    __shared__ float s_list[8][256];
    __shared__ int   s_lc[8];

    const unsigned FULL = 0xFFFFFFFFu;
    const int w = threadIdx.x >> 5, lane = threadIdx.x & 31;
    const int row = blockIdx.x * 8 + w;

    float4 p4 = g_part[(size_t)row * 32 + lane];
    float psum = p4.x, epos = p4.y, ehi = p4.z;
    int pk = __float_as_int(p4.w);
#pragma unroll
    for (int off = 16; off; off >>= 1) {
        psum += __shfl_xor_sync(FULL, psum, off);
        epos += __shfl_xor_sync(FULL, epos, off);
        ehi  += __shfl_xor_sync(FULL, ehi,  off);
        pk   += __shfl_xor_sync(FULL, pk,   off);
    }
    const int pcnt = pk & 0xFFFF, chi = pk >> 16;
    const int labi = labels[row];

    if (!(labi > 0 && pcnt > 0)) {
        if (lane == 0) { g_perrow[row] = 0.0f; g_validf[row] = 0.0f; }
        return;
    }

    const int negcnt = BSZ - 1 - pcnt;
    const int ccnt = g_ccnt[row];
    const float* base = g_cand + (size_t)row * CAP;

    bool slow = (negcnt <= KSEL) || (ccnt > CAP) ||
                !(chi < KSEL && KSEL <= chi + ccnt);
    float E = 0.0f;

    if (!slow) {
        const int kneed = KSEL - chi;
        int c13 = 0, c16 = 0, c19 = 0;
        for (int u = lane; u < ccnt; u += 32) {
            float x = base[u];
            c13 += x > 0.13f; c16 += x > 0.16f; c19 += x > 0.19f;
        }
#pragma unroll
        for (int off = 16; off; off >>= 1) {
            c13 += __shfl_xor_sync(FULL, c13, off);
            c16 += __shfl_xor_sync(FULL, c16, off);
            c19 += __shfl_xor_sync(FULL, c19, off);
        }
        float blo, bhi;
        if (c13 < kneed)      { blo = CLO;   bhi = 0.13f; }
        else if (c16 < kneed) { blo = 0.13f; bhi = 0.16f; }
        else if (c19 < kneed) { blo = 0.16f; bhi = 0.19f; }
        else                  { blo = 0.19f; bhi = CHI;   }

        float own[16]; int nown = 0, ovf = 0;
        for (int u = lane; u < ccnt; u += 32) {
            float x = base[u];
            if (x > blo && x <= bhi) {
                if (nown < 16) own[nown++] = x;
                else ovf = 1;
            }
        }
        if (__ballot_sync(FULL, ovf)) slow = true;

        if (!slow) {
            float T = 0.0f; int gtT = 0, have = 0;
            for (int k = 0; k < nown; k++) {
                float x = own[k];
                int g = 0, e = 0;
                for (int u = 0; u < ccnt; u++) {
                    float y = base[u];
                    g += y > x; e += y == x;
                }
                if (chi + g < KSEL && KSEL <= chi + g + e) { T = x; gtT = g; have = 1; }
            }
            unsigned bal = __ballot_sync(FULL, have);
            if (!bal) slow = true;
            else {
                int src = __ffs(bal) - 1;
                T   = __shfl_sync(FULL, T, src);
                gtT = __shfl_sync(FULL, gtT, src);
                const int ties = KSEL - chi - gtT;
                double ns = 0.0;
                for (int u = lane; u < ccnt; u += 32) {
                    float x = base[u];
                    if (x > T) ns += (double)__expf(10.0f * (x - 1.0f));
                }
#pragma unroll
                for (int off = 16; off; off >>= 1)
                    ns += __shfl_xor_sync(FULL, ns, off);
                E = epos + ehi + (float)ns + (float)ties * __expf(10.0f * (T - 1.0f));
            }
        }
    }

    if (slow) {
        // exact fallback: recompute row dots from F (rare/never on real data)
        float4* fi4 = reinterpret_cast<float4*>(s_fi[w]);
        const float4* F4 = reinterpret_cast<const float4*>(F);
        fi4[lane] = F4[(size_t)row * 32 + lane];
        __syncwarp();
        auto dotj = [&](int j) -> float {
            float a = 0.0f;
            const float4* fj = F4 + (size_t)j * 32;
#pragma unroll 8
            for (int q = 0; q < 32; q++) {
                float4 av = fi4[q]; float4 bv = fj[q];
                a += av.x * bv.x + av.y * bv.y + av.z * bv.z + av.w * bv.w;
            }
            return a;
        };

        if (negcnt <= KSEL) {
            double nsa = 0.0;
            for (int j = lane; j < BSZ; j += 32)
                if (labels[j] != labi)
                    nsa += (double)__expf(10.0f * (dotj(j) - 1.0f));
#pragma unroll
            for (int off = 16; off; off >>= 1)
                nsa += __shfl_xor_sync(FULL, nsa, off);
            E = epos + (float)nsa;
        } else {
            float blo = -1.01f, bhi = 1.01f;
            int cLo = negcnt, cHi = 0;
            for (int round = 0; round < 12 && (cLo - cHi) > 48; round++) {
                float tt[8];
#pragma unroll
                for (int k = 0; k < 8; k++)
                    tt[k] = blo + (bhi - blo) * (float)(k + 1) * (1.0f / 9.0f);
                int cc[8] = {0, 0, 0, 0, 0, 0, 0, 0};
                for (int j = lane; j < BSZ; j += 32)
                    if (labels[j] != labi) {
                        float x = dotj(j);
#pragma unroll
                        for (int k = 0; k < 8; k++) cc[k] += x > tt[k];
                    }
#pragma unroll
                for (int k = 0; k < 8; k++)
#pragma unroll
                    for (int off = 16; off; off >>= 1)
                        cc[k] += __shfl_xor_sync(FULL, cc[k], off);
                int js = 8;
#pragma unroll
                for (int k = 7; k >= 0; k--) if (cc[k] < KSEL) js = k;
                if (js == 8)      { blo = tt[7]; cLo = cc[7]; }
                else if (js == 0) { bhi = tt[0]; cHi = cc[0]; }
                else { blo = tt[js - 1]; cLo = cc[js - 1];
                       bhi = tt[js];     cHi = cc[js]; }
            }
            if (lane == 0) s_lc[w] = 0;
            __syncwarp();
            double nsh = 0.0;
            for (int j = lane; j < BSZ; j += 32)
                if (labels[j] != labi) {
                    float x = dotj(j);
                    if (x > bhi) nsh += (double)__expf(10.0f * (x - 1.0f));
                    else if (x > blo) {
                        int id = atomicAdd(&s_lc[w], 1);
                        if (id < 256) s_list[w][id] = x;
                    }
                }
            __syncwarp();
#pragma unroll
            for (int off = 16; off; off >>= 1)
                nsh += __shfl_xor_sync(FULL, nsh, off);
            int nc = min(s_lc[w], 256);
            float Tf = 0.0f; int gf = 0, hv = 0;
            for (int t2 = lane; t2 < nc; t2 += 32) {
                float x = s_list[w][t2];
                int g = 0, e = 0;
                for (int u = 0; u < nc; u++) {
                    float y = s_list[w][u];
                    g += y > x; e += y == x;
                }
                if (cHi + g < KSEL && KSEL <= cHi + g + e) { Tf = x; gf = g; hv = 1; }
            }
            unsigned bal = __ballot_sync(FULL, hv);
            int src = (bal ? __ffs(bal) - 1 : 0);
            Tf = __shfl_sync(FULL, Tf, src);
            gf = __shfl_sync(FULL, gf, src);
            const int ties = KSEL - cHi - gf;
            double nsb = 0.0;
            for (int t2 = lane; t2 < nc; t2 += 32) {
                float x = s_list[w][t2];
                if (x > Tf) nsb += (double)__expf(10.0f * (x - 1.0f));
            }
#pragma unroll
            for (int off = 16; off; off >>= 1)
                nsb += __shfl_xor_sync(FULL, nsb, off);
            E = epos + (float)nsh + (float)nsb + (float)ties * __expf(10.0f * (Tf - 1.0f));
        }
    }

    if (lane == 0) {
        float pr = -2.0f * (10.0f * (psum / (float)pcnt - 1.0f) - logf(E));
        g_perrow[row] = pr;
        g_validf[row] = 1.0f;
    }
}

// ===========================================================================
// Deterministic final reduction
// ===========================================================================
__global__ void finalize(float* __restrict__ out) {
    __shared__ float sp[256], sv[256];
    int tid = threadIdx.x;
    float ps = 0.0f, vs = 0.0f;
    for (int j = tid; j < BSZ; j += 256) { ps += g_perrow[j]; vs += g_validf[j]; }
    sp[tid] = ps; sv[tid] = vs;
    __syncthreads();
#pragma unroll
    for (int o = 128; o; o >>= 1) {
        if (tid < o) { sp[tid] += sp[tid + o]; sv[tid] += sv[tid + o]; }
        __syncthreads();
    }
    if (tid == 0) out[0] = sp[0] / sv[0];
}

// ===========================================================================
extern "C" void kernel_launch(void* const* d_in, const int* in_sizes, int n_in,
                              void* d_out, int out_size) {
    (void)in_sizes; (void)n_in; (void)out_size;
    const float* F      = (const float*)d_in[0];
    const int*   labels = (const int*)d_in[1];
    float*       out    = (float*)d_out;

    init_k<<<16, 256>>>();
    gemm_stats<<<528, 256>>>(F, labels);
    row_kernel<<<512, 256>>>(F, labels);
    finalize<<<1, 256>>>(out);
}

// round 12
// speedup vs baseline: 2.0291x; 1.7282x over previous
#include <cuda_runtime.h>
#include <math.h>
#include <stdint.h>

#define BSZ  4096
#define KSEL 200
#define CLO  0.10f
#define CHI  0.22f
#define CAP  768

// ---- scratch (__device__ globals; no allocations allowed) ----
__device__ float4 g_part[(size_t)BSZ * 32];     // per (row, tilecol): psum, e_pos, e_hi, packed(pcnt|chi<<16)
__device__ float  g_cand[(size_t)BSZ * CAP];    // negative values in (CLO, CHI]
__device__ int    g_ccnt[BSZ];
__device__ float  g_perrow[BSZ];
__device__ float  g_validf[BSZ];

// packed f32x2 helpers (plain PTX, valid on compute_103)
__device__ __forceinline__ void fma2(unsigned long long& d,
                                     unsigned long long a,
                                     unsigned long long b) {
    asm("fma.rn.f32x2 %0, %1, %2, %0;" : "+l"(d) : "l"(a), "l"(b));
}
__device__ __forceinline__ unsigned long long splat2(float x) {
    unsigned long long r;
    asm("mov.b64 %0, {%1, %1};" : "=l"(r) : "f"(x));
    return r;
}

// ===========================================================================
// init: zero per-row candidate counters (must happen every launch)
// ===========================================================================
__global__ void init_k() {
    int i = blockIdx.x * 256 + threadIdx.x;
    if (i < BSZ) g_ccnt[i] = 0;
}

// ===========================================================================
// Fused GEMM + statistics epilogue (unchanged from R11; proven correct).
// ===========================================================================
__global__ __launch_bounds__(256, 2) void gemm_stats(const float* __restrict__ F,
                                                     const int* __restrict__ labels) {
    int lin = blockIdx.x;
    int by = 0;
    while (lin >= 32 - by) { lin -= 32 - by; by++; }
    int bx = by + lin;
    const int bi = by * 128, bj = bx * 128;

    __shared__ float sh[4224];
    __shared__ int labsh[256];
    float* As = sh;
    float* Bs = sh + 2112;

    const int tid = threadIdx.x;
    const int tx = tid & 15, ty = tid >> 4;

    if (tid < 128) labsh[tid] = labels[bi + tid];
    else           labsh[tid] = labels[bj + tid - 128];

    unsigned long long acc2[4][8];
#pragma unroll
    for (int p = 0; p < 4; p++)
#pragma unroll
        for (int c = 0; c < 8; c++) acc2[p][c] = 0ULL;

    const float4* F4 = reinterpret_cast<const float4*>(F);
    const int kq = tid & 3;
    const int lm = tid >> 2;

#pragma unroll 1
    for (int chunk = 0; chunk < 8; chunk++) {
        __syncthreads();
        float4 va0 = F4[(size_t)(bi + lm) * 32 + chunk * 4 + kq];
        float4 va1 = F4[(size_t)(bi + lm + 64) * 32 + chunk * 4 + kq];
        float4 vb0 = F4[(size_t)(bj + lm) * 32 + chunk * 4 + kq];
        float4 vb1 = F4[(size_t)(bj + lm + 64) * 32 + chunk * 4 + kq];
        {
            int kb = kq * 4;
            As[(kb + 0) * 132 + lm] = va0.x; As[(kb + 1) * 132 + lm] = va0.y;
            As[(kb + 2) * 132 + lm] = va0.z; As[(kb + 3) * 132 + lm] = va0.w;
            As[(kb + 0) * 132 + lm + 64] = va1.x; As[(kb + 1) * 132 + lm + 64] = va1.y;
            As[(kb + 2) * 132 + lm + 64] = va1.z; As[(kb + 3) * 132 + lm + 64] = va1.w;
            Bs[(kb + 0) * 132 + lm] = vb0.x; Bs[(kb + 1) * 132 + lm] = vb0.y;
            Bs[(kb + 2) * 132 + lm] = vb0.z; Bs[(kb + 3) * 132 + lm] = vb0.w;
            Bs[(kb + 0) * 132 + lm + 64] = vb1.x; Bs[(kb + 1) * 132 + lm + 64] = vb1.y;
            Bs[(kb + 2) * 132 + lm + 64] = vb1.z; Bs[(kb + 3) * 132 + lm + 64] = vb1.w;
        }
        __syncthreads();

        const float4* As4 = reinterpret_cast<const float4*>(As);
        const float4* Bs4 = reinterpret_cast<const float4*>(Bs);
#pragma unroll
        for (int k = 0; k < 16; k++) {
            float4 av0 = As4[k * 33 + ty];
            float4 av1 = As4[k * 33 + 16 + ty];
            float4 bv0 = Bs4[k * 33 + tx];
            float4 bv1 = Bs4[k * 33 + 16 + tx];
            unsigned long long A0 = reinterpret_cast<const ulonglong2*>(&av0)->x;
            unsigned long long A1 = reinterpret_cast<const ulonglong2*>(&av0)->y;
            unsigned long long A2 = reinterpret_cast<const ulonglong2*>(&av1)->x;
            unsigned long long A3 = reinterpret_cast<const ulonglong2*>(&av1)->y;
            unsigned long long B[8];
            B[0] = splat2(bv0.x); B[1] = splat2(bv0.y);
            B[2] = splat2(bv0.z); B[3] = splat2(bv0.w);
            B[4] = splat2(bv1.x); B[5] = splat2(bv1.y);
            B[6] = splat2(bv1.z); B[7] = splat2(bv1.w);
#pragma unroll
            for (int c = 0; c < 8; c++) {
                fma2(acc2[0][c], A0, B[c]);
                fma2(acc2[1][c], A1, B[c]);
                fma2(acc2[2][c], A2, B[c]);
                fma2(acc2[3][c], A3, B[c]);
            }
        }
    }

    auto accf = [&](int p, int c, int half) -> float {
        float2 f = *reinterpret_cast<float2*>(&acc2[p][c]);
        return half ? f.y : f.x;
    };
    auto rowOf = [&](int p, int h) -> int {
        return (p < 2) ? (ty * 4 + 2 * p + h) : (64 + ty * 4 + 2 * (p - 2) + h);
    };
    auto colOf = [&](int c) -> int {
        return (c < 4) ? (tx * 4 + c) : (64 + tx * 4 + (c - 4));
    };

    const bool diag = (bx == by);
    __syncthreads();

    // ---- direct role ----
#pragma unroll
    for (int p = 0; p < 4; p++)
#pragma unroll
        for (int h = 0; h < 2; h++) {
            int r = rowOf(p, h);
            int labr = labsh[r];
            float ps = 0.0f, ep = 0.0f, eh = 0.0f;
            int pc = 0, ch = 0;
#pragma unroll
            for (int c = 0; c < 8; c++) {
                float x = accf(p, c, h);
                int cloc = colOf(c);
                if (labsh[128 + cloc] == labr) {
                    if (!(diag && cloc == r)) {
                        ps += x; pc++;
                        ep += __expf(10.0f * (x - 1.0f));
                    }
                } else {
                    if (x > CHI) { eh += __expf(10.0f * (x - 1.0f)); ch++; }
                    else if (x > CLO) {
                        int id = atomicAdd(&g_ccnt[bi + r], 1);
                        if (id < CAP) g_cand[(size_t)(bi + r) * CAP + id] = x;
                    }
                }
            }
            int pk = pc | (ch << 16);
#pragma unroll
            for (int off = 8; off; off >>= 1) {
                ps += __shfl_down_sync(0xFFFFFFFFu, ps, off, 16);
                ep += __shfl_down_sync(0xFFFFFFFFu, ep, off, 16);
                eh += __shfl_down_sync(0xFFFFFFFFu, eh, off, 16);
                pk += __shfl_down_sync(0xFFFFFFFFu, pk, off, 16);
            }
            if (tx == 0)
                g_part[(size_t)(bi + r) * 32 + bx] =
                    make_float4(ps, ep, eh, __int_as_float(pk));
        }

    // ---- mirror role ----
    if (!diag) {
        float2* sh2 = reinterpret_cast<float2*>(sh);
#pragma unroll
        for (int c = 0; c < 8; c++) {
            int cloc = colOf(c);
            int labc = labsh[128 + cloc];
            float ps = 0.0f, ep = 0.0f;
#pragma unroll
            for (int p = 0; p < 4; p++)
#pragma unroll
                for (int h = 0; h < 2; h++) {
                    int r = rowOf(p, h);
                    float x = accf(p, c, h);
                    if (labsh[r] == labc) { ps += x; ep += __expf(10.0f * (x - 1.0f)); }
                }
            sh2[ty * 132 + cloc] = make_float2(ps, ep);
        }
        __syncthreads();
        float mps = 0.0f, mep = 0.0f;
        if (tid < 128)
#pragma unroll
            for (int t = 0; t < 16; t++) {
                float2 v = sh2[t * 132 + tid];
                mps += v.x; mep += v.y;
            }
        __syncthreads();
#pragma unroll
        for (int c = 0; c < 8; c++) {
            int cloc = colOf(c);
            int labc = labsh[128 + cloc];
            float eh = 0.0f;
            int pc = 0, ch = 0;
#pragma unroll
            for (int p = 0; p < 4; p++)
#pragma unroll
                for (int h = 0; h < 2; h++) {
                    int r = rowOf(p, h);
                    float x = accf(p, c, h);
                    if (labsh[r] == labc) { pc++; }
                    else {
                        if (x > CHI) { eh += __expf(10.0f * (x - 1.0f)); ch++; }
                        else if (x > CLO) {
                            int id = atomicAdd(&g_ccnt[bj + cloc], 1);
                            if (id < CAP) g_cand[(size_t)(bj + cloc) * CAP + id] = x;
                        }
                    }
                }
            sh2[ty * 132 + cloc] = make_float2(eh, (float)(pc | (ch << 16)));
        }
        __syncthreads();
        if (tid < 128) {
            float meh = 0.0f, mpk = 0.0f;
#pragma unroll
            for (int t = 0; t < 16; t++) {
                float2 v = sh2[t * 132 + tid];
                meh += v.x; mpk += v.y;
            }
            g_part[(size_t)(bj + tid) * 32 + by] =
                make_float4(mps, mep, meh, __int_as_float((int)mpk));
        }
    }
}

// ===========================================================================
// Row kernel: one warp per row. Fine-threshold bracket (11 cuts, 0.01 wide),
// deterministic ballot-compaction of the bracket into smem, O(bracket^2)
// tie-aware rank with uniform smem reads. Exact slow-path fallback.
// ===========================================================================
__global__ __launch_bounds__(256) void row_kernel(const float* __restrict__ F,
                                                  const int* __restrict__ labels) {
    __shared__ float s_fi[8][128];
    __shared__ float s_list[8][256];
    __shared__ int   s_lc[8];

    const unsigned FULL = 0xFFFFFFFFu;
    const int w = threadIdx.x >> 5, lane = threadIdx.x & 31;
    const int row = blockIdx.x * 8 + w;

    float4 p4 = g_part[(size_t)row * 32 + lane];
    float psum = p4.x, epos = p4.y, ehi = p4.z;
    int pk = __float_as_int(p4.w);
#pragma unroll
    for (int off = 16; off; off >>= 1) {
        psum += __shfl_xor_sync(FULL, psum, off);
        epos += __shfl_xor_sync(FULL, epos, off);
        ehi  += __shfl_xor_sync(FULL, ehi,  off);
        pk   += __shfl_xor_sync(FULL, pk,   off);
    }
    const int pcnt = pk & 0xFFFF, chi = pk >> 16;
    const int labi = labels[row];

    if (!(labi > 0 && pcnt > 0)) {
        if (lane == 0) { g_perrow[row] = 0.0f; g_validf[row] = 0.0f; }
        return;
    }

    const int negcnt = BSZ - 1 - pcnt;
    const int ccnt = g_ccnt[row];
    const float* base = g_cand + (size_t)row * CAP;

    bool slow = (negcnt <= KSEL) || (ccnt > CAP) ||
                !(chi < KSEL && KSEL <= chi + ccnt);
    float E = 0.0f;

    if (!slow) {
        const int kneed = KSEL - chi;

        // ---- pass 1: counts above 11 fine thresholds (coalesced global) ----
        int ct[11];
#pragma unroll
        for (int j = 0; j < 11; j++) ct[j] = 0;
        for (int u = lane; u < ccnt; u += 32) {
            float x = base[u];
#pragma unroll
            for (int j = 0; j < 11; j++)
                ct[j] += x > (0.11f + 0.01f * (float)j);
        }
#pragma unroll
        for (int j = 0; j < 11; j++)
#pragma unroll
            for (int off = 16; off; off >>= 1)
                ct[j] += __shfl_xor_sync(FULL, ct[j], off);

        // ---- bracket (blo, bhi]: smallest j with ct[j] < kneed ----
        float blo = 0.21f, bhi = CHI;
        int cAwin = 0;                        // count in window above bhi
#pragma unroll
        for (int j = 10; j >= 0; j--)
            if (ct[j] < kneed) {
                bhi = 0.11f + 0.01f * (float)j;
                blo = (j == 0) ? CLO : (0.11f + 0.01f * (float)(j - 1));
                cAwin = ct[j];
            }
        const int cAbove = chi + cAwin;       // total negatives above bhi

        // ---- pass 2: deterministic ballot-compaction of bracket into smem ----
        int nlist = 0;
        int iters = (ccnt + 31) & ~31;
        for (int ub = 0; ub < iters; ub += 32) {
            int u = ub + lane;
            float x = (u < ccnt) ? base[u] : -1.0f;
            bool pred = (x > blo) && (x <= bhi);
            unsigned bal = __ballot_sync(FULL, pred);
            int pos = nlist + __popc(bal & ((1u << lane) - 1u));
            if (pred && pos < 256) s_list[w][pos] = x;
            nlist += __popc(bal);
        }
        if (nlist > 256) slow = true;
        __syncwarp();

        if (!slow) {
            // ---- tie-aware rank within the bracket (uniform smem loop) ----
            float T = 0.0f; int gtT = 0, have = 0;
            for (int t = lane; t < nlist; t += 32) {
                float x = s_list[w][t];
                int g = 0, e = 0;
                for (int u = 0; u < nlist; u++) {
                    float y = s_list[w][u];
                    g += y > x; e += y == x;
                }
                int tg = cAbove + g;
                if (tg < KSEL && KSEL <= tg + e) { T = x; gtT = tg; have = 1; }
            }
            unsigned bal = __ballot_sync(FULL, have);
            if (!bal) slow = true;
            else {
                int src = __ffs(bal) - 1;
                T   = __shfl_sync(FULL, T, src);
                gtT = __shfl_sync(FULL, gtT, src);
                const int ties = KSEL - gtT;
                double ns = 0.0;
                for (int u = lane; u < ccnt; u += 32) {
                    float x = base[u];
                    if (x > T) ns += (double)__expf(10.0f * (x - 1.0f));
                }
#pragma unroll
                for (int off = 16; off; off >>= 1)
                    ns += __shfl_xor_sync(FULL, ns, off);
                E = epos + ehi + (float)ns + (float)ties * __expf(10.0f * (T - 1.0f));
            }
        }
    }

    if (slow) {
        // exact fallback: recompute row dots from F (rare/never on real data)
        float4* fi4 = reinterpret_cast<float4*>(s_fi[w]);
        const float4* F4 = reinterpret_cast<const float4*>(F);
        fi4[lane] = F4[(size_t)row * 32 + lane];
        __syncwarp();
        auto dotj = [&](int j) -> float {
            float a = 0.0f;
            const float4* fj = F4 + (size_t)j * 32;
#pragma unroll 8
            for (int q = 0; q < 32; q++) {
                float4 av = fi4[q]; float4 bv = fj[q];
                a += av.x * bv.x + av.y * bv.y + av.z * bv.z + av.w * bv.w;
            }
            return a;
        };

        if (negcnt <= KSEL) {
            double nsa = 0.0;
            for (int j = lane; j < BSZ; j += 32)
                if (labels[j] != labi)
                    nsa += (double)__expf(10.0f * (dotj(j) - 1.0f));
#pragma unroll
            for (int off = 16; off; off >>= 1)
                nsa += __shfl_xor_sync(FULL, nsa, off);
            E = epos + (float)nsa;
        } else {
            float blo = -1.01f, bhi = 1.01f;
            int cLo = negcnt, cHi = 0;
            for (int round = 0; round < 12 && (cLo - cHi) > 48; round++) {
                float tt[8];
#pragma unroll
                for (int k = 0; k < 8; k++)
                    tt[k] = blo + (bhi - blo) * (float)(k + 1) * (1.0f / 9.0f);
                int cc[8] = {0, 0, 0, 0, 0, 0, 0, 0};
                for (int j = lane; j < BSZ; j += 32)
                    if (labels[j] != labi) {
                        float x = dotj(j);
#pragma unroll
                        for (int k = 0; k < 8; k++) cc[k] += x > tt[k];
                    }
#pragma unroll
                for (int k = 0; k < 8; k++)
#pragma unroll
                    for (int off = 16; off; off >>= 1)
                        cc[k] += __shfl_xor_sync(FULL, cc[k], off);
                int js = 8;
#pragma unroll
                for (int k = 7; k >= 0; k--) if (cc[k] < KSEL) js = k;
                if (js == 8)      { blo = tt[7]; cLo = cc[7]; }
                else if (js == 0) { bhi = tt[0]; cHi = cc[0]; }
                else { blo = tt[js - 1]; cLo = cc[js - 1];
                       bhi = tt[js];     cHi = cc[js]; }
            }
            if (lane == 0) s_lc[w] = 0;
            __syncwarp();
            double nsh = 0.0;
            for (int j = lane; j < BSZ; j += 32)
                if (labels[j] != labi) {
                    float x = dotj(j);
                    if (x > bhi) nsh += (double)__expf(10.0f * (x - 1.0f));
                    else if (x > blo) {
                        int id = atomicAdd(&s_lc[w], 1);
                        if (id < 256) s_list[w][id] = x;
                    }
                }
            __syncwarp();
#pragma unroll
            for (int off = 16; off; off >>= 1)
                nsh += __shfl_xor_sync(FULL, nsh, off);
            int nc = min(s_lc[w], 256);
            float Tf = 0.0f; int gf = 0, hv = 0;
            for (int t2 = lane; t2 < nc; t2 += 32) {
                float x = s_list[w][t2];
                int g = 0, e = 0;
                for (int u = 0; u < nc; u++) {
                    float y = s_list[w][u];
                    g += y > x; e += y == x;
                }
                if (cHi + g < KSEL && KSEL <= cHi + g + e) { Tf = x; gf = g; hv = 1; }
            }
            unsigned bal = __ballot_sync(FULL, hv);
            int src = (bal ? __ffs(bal) - 1 : 0);
            Tf = __shfl_sync(FULL, Tf, src);
            gf = __shfl_sync(FULL, gf, src);
            const int ties = KSEL - cHi - gf;
            double nsb = 0.0;
            for (int t2 = lane; t2 < nc; t2 += 32) {
                float x = s_list[w][t2];
                if (x > Tf) nsb += (double)__expf(10.0f * (x - 1.0f));
            }
#pragma unroll
            for (int off = 16; off; off >>= 1)
                nsb += __shfl_xor_sync(FULL, nsb, off);
            E = epos + (float)nsh + (float)nsb + (float)ties * __expf(10.0f * (Tf - 1.0f));
        }
    }

    if (lane == 0) {
        float pr = -2.0f * (10.0f * (psum / (float)pcnt - 1.0f) - logf(E));
        g_perrow[row] = pr;
        g_validf[row] = 1.0f;
    }
}

// ===========================================================================
// Deterministic final reduction
// ===========================================================================
__global__ void finalize(float* __restrict__ out) {
    __shared__ float sp[256], sv[256];
    int tid = threadIdx.x;
    float ps = 0.0f, vs = 0.0f;
    for (int j = tid; j < BSZ; j += 256) { ps += g_perrow[j]; vs += g_validf[j]; }
    sp[tid] = ps; sv[tid] = vs;
    __syncthreads();
#pragma unroll
    for (int o = 128; o; o >>= 1) {
        if (tid < o) { sp[tid] += sp[tid + o]; sv[tid] += sv[tid + o]; }
        __syncthreads();
    }
    if (tid == 0) out[0] = sp[0] / sv[0];
}

// ===========================================================================
extern "C" void kernel_launch(void* const* d_in, const int* in_sizes, int n_in,
                              void* d_out, int out_size) {
    (void)in_sizes; (void)n_in; (void)out_size;
    const float* F      = (const float*)d_in[0];
    const int*   labels = (const int*)d_in[1];
    float*       out    = (float*)d_out;

    init_k<<<16, 256>>>();
    gemm_stats<<<528, 256>>>(F, labels);
    row_kernel<<<512, 256>>>(F, labels);
    finalize<<<1, 256>>>(out);
}

// round 15
// speedup vs baseline: 2.0498x; 1.0102x over previous
#include <cuda_runtime.h>
#include <math.h>
#include <stdint.h>

#define BSZ  4096
#define KSEL 200
#define CLO  0.10f
#define CHI  0.22f
#define CAP  768

// ---- scratch (__device__ globals; no allocations allowed) ----
__device__ float  g_Ft[(size_t)32 * 128 * 128];  // k-major tiles: [block][k][row], 2 MB
__device__ float4 g_part[(size_t)BSZ * 32];      // per (row, tilecol): psum, e_pos, e_hi, packed
__device__ float  g_cand[(size_t)BSZ * CAP];     // negative values in (CLO, CHI]
__device__ int    g_ccnt[BSZ];                   // zero-init; row_kernel re-zeroes after use
__device__ float  g_perrow[BSZ];
__device__ float  g_validf[BSZ];
__device__ int    g_done;                        // zero-init; last block resets

// packed f32x2 helpers (plain PTX, valid on compute_103)
__device__ __forceinline__ void fma2(unsigned long long& d,
                                     unsigned long long a,
                                     unsigned long long b) {
    asm("fma.rn.f32x2 %0, %1, %2, %0;" : "+l"(d) : "l"(a), "l"(b));
}
__device__ __forceinline__ unsigned long long splat2(float x) {
    unsigned long long r;
    asm("mov.b64 %0, {%1, %1};" : "=l"(r) : "f"(x));
    return r;
}
__device__ __forceinline__ void cp16(uint32_t dst_smem, const void* src) {
    asm volatile("cp.async.cg.shared.global [%0], [%1], 16;"
                 :: "r"(dst_smem), "l"(src) : "memory");
}

// ===========================================================================
// Transpose F (row-major [4096][128]) into k-major 128-row blocks g_Ft.
// ===========================================================================
__global__ void transpose_k(const float* __restrict__ F) {
    __shared__ float t[32][33];
    const int b  = blockIdx.z;
    const int rt = blockIdx.x * 32, kt = blockIdx.y * 32;
    const int tx = threadIdx.x, ty = threadIdx.y;
#pragma unroll
    for (int i = 0; i < 32; i += 8)
        t[ty + i][tx] = F[(size_t)(b * 128 + rt + ty + i) * 128 + kt + tx];
    __syncthreads();
#pragma unroll
    for (int i = 0; i < 32; i += 8)
        g_Ft[(size_t)b * 16384 + (kt + ty + i) * 128 + rt + tx] = t[tx][ty + i];
}

// ===========================================================================
// Fused GEMM + statistics epilogue. 128x128 tiles, triangular grid (528).
// cp.async 2-stage pipeline over 4 chunks of K=32; no smem transpose.
// Epilogue (unchanged logic): per-(row,tilecol) partials + candidate appends.
// ===========================================================================
#define KCH 32
#define STG_F 8448                               // floats per stage (A 4224 + B 4224)

__global__ __launch_bounds__(256, 2) void gemm_stats(const int* __restrict__ labels) {
    extern __shared__ float smem[];
    __shared__ int labsh[256];

    int lin = blockIdx.x;
    int by = 0;
    while (lin >= 32 - by) { lin -= 32 - by; by++; }
    int bx = by + lin;
    const int bi = by * 128, bj = bx * 128;

    const int tid = threadIdx.x;
    const int tx = tid & 15, ty = tid >> 4;

    if (tid < 128) labsh[tid] = labels[bi + tid];
    else           labsh[tid] = labels[bj + tid - 128];

    unsigned long long acc2[4][8];
#pragma unroll
    for (int p = 0; p < 4; p++)
#pragma unroll
        for (int c = 0; c < 8; c++) acc2[p][c] = 0ULL;

    const float* srcA = g_Ft + (size_t)by * 16384;
    const float* srcB = g_Ft + (size_t)bx * 16384;
    const uint32_t sbase = (uint32_t)__cvta_generic_to_shared(smem);

    // issue chunk c into stage s: 1024 16B-chunks per tile, 4 per thread
    auto issue = [&](int c, int s) {
        uint32_t stg = sbase + (uint32_t)(s * STG_F * 4);
#pragma unroll
        for (int i = 0; i < 4; i++) {
            int id = tid + i * 256;              // 0..1023
            int k = id >> 5, rq = id & 31;
            uint32_t off = (uint32_t)((k * 132 + rq * 4) * 4);
            const float* sA = srcA + (c * KCH + k) * 128 + rq * 4;
            const float* sB = srcB + (c * KCH + k) * 128 + rq * 4;
            cp16(stg + off, sA);
            cp16(stg + 4224 * 4 + off, sB);
        }
        asm volatile("cp.async.commit_group;" ::: "memory");
    };

    issue(0, 0);
#pragma unroll 1
    for (int c = 0; c < 4; c++) {
        if (c < 3) issue(c + 1, (c + 1) & 1);
        if (c < 3) asm volatile("cp.async.wait_group 1;" ::: "memory");
        else       asm volatile("cp.async.wait_group 0;" ::: "memory");
        __syncthreads();
        const float4* As4 = reinterpret_cast<const float4*>(smem + (c & 1) * STG_F);
        const float4* Bs4 = As4 + 1056;
#pragma unroll 8
        for (int k = 0; k < KCH; k++) {
            float4 av0 = As4[k * 33 + ty];
            float4 av1 = As4[k * 33 + 16 + ty];
            float4 bv0 = Bs4[k * 33 + tx];
            float4 bv1 = Bs4[k * 33 + 16 + tx];
            unsigned long long A0 = reinterpret_cast<const ulonglong2*>(&av0)->x;
            unsigned long long A1 = reinterpret_cast<const ulonglong2*>(&av0)->y;
            unsigned long long A2 = reinterpret_cast<const ulonglong2*>(&av1)->x;
            unsigned long long A3 = reinterpret_cast<const ulonglong2*>(&av1)->y;
            unsigned long long B[8];
            B[0] = splat2(bv0.x); B[1] = splat2(bv0.y);
            B[2] = splat2(bv0.z); B[3] = splat2(bv0.w);
            B[4] = splat2(bv1.x); B[5] = splat2(bv1.y);
            B[6] = splat2(bv1.z); B[7] = splat2(bv1.w);
#pragma unroll
            for (int cc = 0; cc < 8; cc++) {
                fma2(acc2[0][cc], A0, B[cc]);
                fma2(acc2[1][cc], A1, B[cc]);
                fma2(acc2[2][cc], A2, B[cc]);
                fma2(acc2[3][cc], A3, B[cc]);
            }
        }
        __syncthreads();
    }

    auto accf = [&](int p, int c, int half) -> float {
        float2 f = *reinterpret_cast<float2*>(&acc2[p][c]);
        return half ? f.y : f.x;
    };
    auto rowOf = [&](int p, int h) -> int {
        return (p < 2) ? (ty * 4 + 2 * p + h) : (64 + ty * 4 + 2 * (p - 2) + h);
    };
    auto colOf = [&](int c) -> int {
        return (c < 4) ? (tx * 4 + c) : (64 + tx * 4 + (c - 4));
    };

    const bool diag = (bx == by);

    // ---- direct role: rows in block by, tilecol bx (unique writer) ----
#pragma unroll
    for (int p = 0; p < 4; p++)
#pragma unroll
        for (int h = 0; h < 2; h++) {
            int r = rowOf(p, h);
            int labr = labsh[r];
            float ps = 0.0f, ep = 0.0f, eh = 0.0f;
            int pc = 0, ch = 0;
#pragma unroll
            for (int c = 0; c < 8; c++) {
                float x = accf(p, c, h);
                int cloc = colOf(c);
                if (labsh[128 + cloc] == labr) {
                    if (!(diag && cloc == r)) {
                        ps += x; pc++;
                        ep += __expf(10.0f * (x - 1.0f));
                    }
                } else {
                    if (x > CHI) { eh += __expf(10.0f * (x - 1.0f)); ch++; }
                    else if (x > CLO) {
                        int id = atomicAdd(&g_ccnt[bi + r], 1);
                        if (id < CAP) g_cand[(size_t)(bi + r) * CAP + id] = x;
                    }
                }
            }
            int pk = pc | (ch << 16);
#pragma unroll
            for (int off = 8; off; off >>= 1) {
                ps += __shfl_down_sync(0xFFFFFFFFu, ps, off, 16);
                ep += __shfl_down_sync(0xFFFFFFFFu, ep, off, 16);
                eh += __shfl_down_sync(0xFFFFFFFFu, eh, off, 16);
                pk += __shfl_down_sync(0xFFFFFFFFu, pk, off, 16);
            }
            if (tx == 0)
                g_part[(size_t)(bi + r) * 32 + bx] =
                    make_float4(ps, ep, eh, __int_as_float(pk));
        }

    // ---- mirror role: rows in block bx, tilecol by (off-diagonal only) ----
    if (!diag) {
        float2* sh2 = reinterpret_cast<float2*>(smem);
#pragma unroll
        for (int c = 0; c < 8; c++) {
            int cloc = colOf(c);
            int labc = labsh[128 + cloc];
            float ps = 0.0f, ep = 0.0f;
#pragma unroll
            for (int p = 0; p < 4; p++)
#pragma unroll
                for (int h = 0; h < 2; h++) {
                    int r = rowOf(p, h);
                    float x = accf(p, c, h);
                    if (labsh[r] == labc) { ps += x; ep += __expf(10.0f * (x - 1.0f)); }
                }
            sh2[ty * 132 + cloc] = make_float2(ps, ep);
        }
        __syncthreads();
        float mps = 0.0f, mep = 0.0f;
        if (tid < 128)
#pragma unroll
            for (int t = 0; t < 16; t++) {
                float2 v = sh2[t * 132 + tid];
                mps += v.x; mep += v.y;
            }
        __syncthreads();
#pragma unroll
        for (int c = 0; c < 8; c++) {
            int cloc = colOf(c);
            int labc = labsh[128 + cloc];
            float eh = 0.0f;
            int pc = 0, ch = 0;
#pragma unroll
            for (int p = 0; p < 4; p++)
#pragma unroll
                for (int h = 0; h < 2; h++) {
                    int r = rowOf(p, h);
                    float x = accf(p, c, h);
                    if (labsh[r] == labc) { pc++; }
                    else {
                        if (x > CHI) { eh += __expf(10.0f * (x - 1.0f)); ch++; }
                        else if (x > CLO) {
                            int id = atomicAdd(&g_ccnt[bj + cloc], 1);
                            if (id < CAP) g_cand[(size_t)(bj + cloc) * CAP + id] = x;
                        }
                    }
                }
            sh2[ty * 132 + cloc] = make_float2(eh, (float)(pc | (ch << 16)));
        }
        __syncthreads();
        if (tid < 128) {
            float meh = 0.0f, mpk = 0.0f;
#pragma unroll
            for (int t = 0; t < 16; t++) {
                float2 v = sh2[t * 132 + tid];
                meh += v.x; mpk += v.y;
            }
            g_part[(size_t)(bj + tid) * 32 + by] =
                make_float4(mps, mep, meh, __int_as_float((int)mpk));
        }
    }
}

// ===========================================================================
// Row kernel: one warp per row (8 rows/block, 512 blocks). Fine-threshold
// bracket, ballot-compaction, O(bracket^2) smem rank. Exact slow fallback.
// Last block performs the deterministic final reduction (finalize merged).
// ===========================================================================
__global__ __launch_bounds__(256) void row_kernel(const float* __restrict__ F,
                                                  const int* __restrict__ labels,
                                                  float* __restrict__ out) {
    __shared__ float s_fi[8][128];
    __shared__ float s_list[8][256];
    __shared__ int   s_lc[8];
    __shared__ float sp[256], sv[256];
    __shared__ int   lastf;

    const unsigned FULL = 0xFFFFFFFFu;
    const int w = threadIdx.x >> 5, lane = threadIdx.x & 31;
    const int row = blockIdx.x * 8 + w;

    float4 p4 = g_part[(size_t)row * 32 + lane];
    float psum = p4.x, epos = p4.y, ehi = p4.z;
    int pk = __float_as_int(p4.w);
#pragma unroll
    for (int off = 16; off; off >>= 1) {
        psum += __shfl_xor_sync(FULL, psum, off);
        epos += __shfl_xor_sync(FULL, epos, off);
        ehi  += __shfl_xor_sync(FULL, ehi,  off);
        pk   += __shfl_xor_sync(FULL, pk,   off);
    }
    const int pcnt = pk & 0xFFFF, chi = pk >> 16;
    const int labi = labels[row];
    const bool active = (labi > 0) && (pcnt > 0);

    if (!active) {
        if (lane == 0) { g_perrow[row] = 0.0f; g_validf[row] = 0.0f; }
    } else {
        const int negcnt = BSZ - 1 - pcnt;
        const int ccnt = g_ccnt[row];
        const float* base = g_cand + (size_t)row * CAP;

        bool slow = (negcnt <= KSEL) || (ccnt > CAP) ||
                    !(chi < KSEL && KSEL <= chi + ccnt);
        float E = 0.0f;

        if (!slow) {
            const int kneed = KSEL - chi;
            int ct[11];
#pragma unroll
            for (int j = 0; j < 11; j++) ct[j] = 0;
            for (int u = lane; u < ccnt; u += 32) {
                float x = base[u];
#pragma unroll
                for (int j = 0; j < 11; j++)
                    ct[j] += x > (0.11f + 0.01f * (float)j);
            }
#pragma unroll
            for (int j = 0; j < 11; j++)
#pragma unroll
                for (int off = 16; off; off >>= 1)
                    ct[j] += __shfl_xor_sync(FULL, ct[j], off);

            float blo = 0.21f, bhi = CHI;
            int cAwin = 0;
#pragma unroll
            for (int j = 10; j >= 0; j--)
                if (ct[j] < kneed) {
                    bhi = 0.11f + 0.01f * (float)j;
                    blo = (j == 0) ? CLO : (0.11f + 0.01f * (float)(j - 1));
                    cAwin = ct[j];
                }
            const int cAbove = chi + cAwin;

            int nlist = 0;
            int iters = (ccnt + 31) & ~31;
            for (int ub = 0; ub < iters; ub += 32) {
                int u = ub + lane;
                float x = (u < ccnt) ? base[u] : -1.0f;
                bool pred = (x > blo) && (x <= bhi);
                unsigned bal = __ballot_sync(FULL, pred);
                int pos = nlist + __popc(bal & ((1u << lane) - 1u));
                if (pred && pos < 256) s_list[w][pos] = x;
                nlist += __popc(bal);
            }
            if (nlist > 256) slow = true;
            __syncwarp();

            if (!slow) {
                float T = 0.0f; int gtT = 0, have = 0;
                for (int t = lane; t < nlist; t += 32) {
                    float x = s_list[w][t];
                    int g = 0, e = 0;
                    for (int u = 0; u < nlist; u++) {
                        float y = s_list[w][u];
                        g += y > x; e += y == x;
                    }
                    int tg = cAbove + g;
                    if (tg < KSEL && KSEL <= tg + e) { T = x; gtT = tg; have = 1; }
                }
                unsigned bal = __ballot_sync(FULL, have);
                if (!bal) slow = true;
                else {
                    int src = __ffs(bal) - 1;
                    T   = __shfl_sync(FULL, T, src);
                    gtT = __shfl_sync(FULL, gtT, src);
                    const int ties = KSEL - gtT;
                    double ns = 0.0;
                    for (int u = lane; u < ccnt; u += 32) {
                        float x = base[u];
                        if (x > T) ns += (double)__expf(10.0f * (x - 1.0f));
                    }
#pragma unroll
                    for (int off = 16; off; off >>= 1)
                        ns += __shfl_xor_sync(FULL, ns, off);
                    E = epos + ehi + (float)ns + (float)ties * __expf(10.0f * (T - 1.0f));
                }
            }
        }

        if (slow) {
            float4* fi4 = reinterpret_cast<float4*>(s_fi[w]);
            const float4* F4 = reinterpret_cast<const float4*>(F);
            fi4[lane] = F4[(size_t)row * 32 + lane];
            __syncwarp();
            auto dotj = [&](int j) -> float {
                float a = 0.0f;
                const float4* fj = F4 + (size_t)j * 32;
#pragma unroll 8
                for (int q = 0; q < 32; q++) {
                    float4 av = fi4[q]; float4 bv = fj[q];
                    a += av.x * bv.x + av.y * bv.y + av.z * bv.z + av.w * bv.w;
                }
                return a;
            };

            if (negcnt <= KSEL) {
                double nsa = 0.0;
                for (int j = lane; j < BSZ; j += 32)
                    if (labels[j] != labi)
                        nsa += (double)__expf(10.0f * (dotj(j) - 1.0f));
#pragma unroll
                for (int off = 16; off; off >>= 1)
                    nsa += __shfl_xor_sync(FULL, nsa, off);
                E = epos + (float)nsa;
            } else {
                float blo = -1.01f, bhi = 1.01f;
                int cLo = negcnt, cHi = 0;
                for (int round = 0; round < 12 && (cLo - cHi) > 48; round++) {
                    float tt[8];
#pragma unroll
                    for (int k = 0; k < 8; k++)
                        tt[k] = blo + (bhi - blo) * (float)(k + 1) * (1.0f / 9.0f);
                    int cc[8] = {0, 0, 0, 0, 0, 0, 0, 0};
                    for (int j = lane; j < BSZ; j += 32)
                        if (labels[j] != labi) {
                            float x = dotj(j);
#pragma unroll
                            for (int k = 0; k < 8; k++) cc[k] += x > tt[k];
                        }
#pragma unroll
                    for (int k = 0; k < 8; k++)
#pragma unroll
                        for (int off = 16; off; off >>= 1)
                            cc[k] += __shfl_xor_sync(FULL, cc[k], off);
                    int js = 8;
#pragma unroll
                    for (int k = 7; k >= 0; k--) if (cc[k] < KSEL) js = k;
                    if (js == 8)      { blo = tt[7]; cLo = cc[7]; }
                    else if (js == 0) { bhi = tt[0]; cHi = cc[0]; }
                    else { blo = tt[js - 1]; cLo = cc[js - 1];
                           bhi = tt[js];     cHi = cc[js]; }
                }
                if (lane == 0) s_lc[w] = 0;
                __syncwarp();
                double nsh = 0.0;
                for (int j = lane; j < BSZ; j += 32)
                    if (labels[j] != labi) {
                        float x = dotj(j);
                        if (x > bhi) nsh += (double)__expf(10.0f * (x - 1.0f));
                        else if (x > blo) {
                            int id = atomicAdd(&s_lc[w], 1);
                            if (id < 256) s_list[w][id] = x;
                        }
                    }
                __syncwarp();
#pragma unroll
                for (int off = 16; off; off >>= 1)
                    nsh += __shfl_xor_sync(FULL, nsh, off);
                int nc = min(s_lc[w], 256);
                float Tf = 0.0f; int gf = 0, hv = 0;
                for (int t2 = lane; t2 < nc; t2 += 32) {
                    float x = s_list[w][t2];
                    int g = 0, e = 0;
                    for (int u = 0; u < nc; u++) {
                        float y = s_list[w][u];
                        g += y > x; e += y == x;
                    }
                    if (cHi + g < KSEL && KSEL <= cHi + g + e) { Tf = x; gf = g; hv = 1; }
                }
                unsigned bal = __ballot_sync(FULL, hv);
                int src = (bal ? __ffs(bal) - 1 : 0);
                Tf = __shfl_sync(FULL, Tf, src);
                gf = __shfl_sync(FULL, gf, src);
                const int ties = KSEL - cHi - gf;
                double nsb = 0.0;
                for (int t2 = lane; t2 < nc; t2 += 32) {
                    float x = s_list[w][t2];
                    if (x > Tf) nsb += (double)__expf(10.0f * (x - 1.0f));
                }
#pragma unroll
                for (int off = 16; off; off >>= 1)
                    nsb += __shfl_xor_sync(FULL, nsb, off);
                E = epos + (float)nsh + (float)nsb + (float)ties * __expf(10.0f * (Tf - 1.0f));
            }
        }

        if (lane == 0) {
            float pr = -2.0f * (10.0f * (psum / (float)pcnt - 1.0f) - logf(E));
            g_perrow[row] = pr;
            g_validf[row] = 1.0f;
        }
    }

    // reset candidate counter for the next (graph-replayed) launch
    if (lane == 0) g_ccnt[row] = 0;

    // ---- merged finalize: last block does the deterministic reduction ----
    __threadfence();
    __syncthreads();
    if (threadIdx.x == 0)
        lastf = (atomicAdd(&g_done, 1) == (int)gridDim.x - 1);
    __syncthreads();
    if (lastf) {
        int tid = threadIdx.x;
        float ps = 0.0f, vs = 0.0f;
        for (int j = tid; j < BSZ; j += 256) { ps += g_perrow[j]; vs += g_validf[j]; }
        sp[tid] = ps; sv[tid] = vs;
        __syncthreads();
#pragma unroll
        for (int o = 128; o; o >>= 1) {
            if (tid < o) { sp[tid] += sp[tid + o]; sv[tid] += sv[tid + o]; }
            __syncthreads();
        }
        if (tid == 0) {
            out[0] = sp[0] / sv[0];
            g_done = 0;
        }
    }
}

// ===========================================================================
extern "C" void kernel_launch(void* const* d_in, const int* in_sizes, int n_in,
                              void* d_out, int out_size) {
    (void)in_sizes; (void)n_in; (void)out_size;
    const float* F      = (const float*)d_in[0];
    const int*   labels = (const int*)d_in[1];
    float*       out    = (float*)d_out;

    cudaFuncSetAttribute(gemm_stats, cudaFuncAttributeMaxDynamicSharedMemorySize,
                         2 * STG_F * 4);

    transpose_k<<<dim3(4, 4, 32), dim3(32, 8)>>>(F);
    gemm_stats<<<528, 256, 2 * STG_F * 4>>>(labels);
    row_kernel<<<512, 256>>>(F, labels, out);
}